// round 10
// baseline (speedup 1.0000x reference)
#include <cuda_runtime.h>
#include <cuda_bf16.h>
#include <math_constants.h>
#include <cstdint>

// Problem constants
#define T_DIM 1024
#define B_DIM 4
#define C_DIM 1024
#define H_DIM 16
#define D_DIM 64
#define P_DIM 2047
#define BT_DIM (B_DIM * T_DIM)

// Scratch (device globals). Row order m = t*B + b ([T,B,C] natural).
__device__ __nv_bfloat16 g_quh[BT_DIM * C_DIM];  // (q@Wq+bq+pbu)*0.125 hi
__device__ __nv_bfloat16 g_qul[BT_DIM * C_DIM];  // lo
__device__ __nv_bfloat16 g_kh[BT_DIM * C_DIM];
__device__ __nv_bfloat16 g_kl[BT_DIM * C_DIM];
__device__ __nv_bfloat16 g_vh[BT_DIM * C_DIM];
__device__ __nv_bfloat16 g_vl[BT_DIM * C_DIM];
__device__ __nv_bfloat16 g_ph[P_DIM * C_DIM];
__device__ __nv_bfloat16 g_pl[P_DIM * C_DIM];
__device__ __nv_bfloat16 g_xh[BT_DIM * C_DIM];
__device__ __nv_bfloat16 g_xl[BT_DIM * C_DIM];
// Pre-split GEMM operands
#define OWQ 0
#define OWK 1048576
#define OWV 2097152
#define OWP 3145728
#define OWO 4194304
__device__ __nv_bfloat16 g_wh[5 * 1048576];
__device__ __nv_bfloat16 g_wl[5 * 1048576];
#define OIQ 0
#define OIK 4194304
#define OIV 8388608
#define OIP 12582912
__device__ __nv_bfloat16 g_inh[14679040];
__device__ __nv_bfloat16 g_inl[14679040];

// ---------------------------------------------------------------------------
// Helpers
// ---------------------------------------------------------------------------
__device__ __forceinline__ uint32_t smem_u32(const void* p) {
    uint32_t a;
    asm("{ .reg .u64 t; cvta.to.shared.u64 t, %1; cvt.u32.u64 %0, t; }" : "=r"(a) : "l"(p));
    return a;
}
__device__ __forceinline__ void cp_async16(uint32_t saddr, const void* gptr, bool pred) {
    const int sz = pred ? 16 : 0;
    asm volatile("cp.async.cg.shared.global [%0], [%1], 16, %2;"
                 :: "r"(saddr), "l"(gptr), "r"(sz));
}
__device__ __forceinline__ void cp_commit() { asm volatile("cp.async.commit_group;"); }
template <int N>
__device__ __forceinline__ void cp_wait() { asm volatile("cp.async.wait_group %0;" :: "n"(N)); }

__device__ __forceinline__ void ldsm_x4(uint32_t* r, uint32_t a) {
    asm volatile("ldmatrix.sync.aligned.m8n8.x4.shared.b16 {%0,%1,%2,%3}, [%4];"
                 : "=r"(r[0]), "=r"(r[1]), "=r"(r[2]), "=r"(r[3]) : "r"(a));
}
__device__ __forceinline__ void ldsm_x4t(uint32_t* r, uint32_t a) {
    asm volatile("ldmatrix.sync.aligned.m8n8.x4.trans.shared.b16 {%0,%1,%2,%3}, [%4];"
                 : "=r"(r[0]), "=r"(r[1]), "=r"(r[2]), "=r"(r[3]) : "r"(a));
}
__device__ __forceinline__ void mma_bf16(float* c, const uint32_t* a, const uint32_t* b) {
    asm volatile("mma.sync.aligned.m16n8k16.row.col.f32.bf16.bf16.f32 "
                 "{%0,%1,%2,%3}, {%4,%5,%6,%7}, {%8,%9}, {%0,%1,%2,%3};"
                 : "+f"(c[0]), "+f"(c[1]), "+f"(c[2]), "+f"(c[3])
                 : "r"(a[0]), "r"(a[1]), "r"(a[2]), "r"(a[3]), "r"(b[0]), "r"(b[1]));
}
__device__ __forceinline__ uint32_t us16(__nv_bfloat16 h) { return (uint32_t)__bfloat16_as_ushort(h); }

// Padded-pitch fragment addressing (attention kernel)
__device__ __forceinline__ uint32_t a_addr(uint32_t base, int row0, int k0, int lane, int pitch) {
    const int row = row0 + (lane & 15);
    const int col = k0 + ((lane >> 4) << 3);
    return base + (uint32_t)((row * pitch + col) * 2);
}
__device__ __forceinline__ uint32_t b_addr(uint32_t base, int n0, int k0, int lane, int pitch) {
    const int row = n0 + (lane & 7) + ((lane >> 4) << 3);
    const int col = k0 + (lane & 8);
    return base + (uint32_t)((row * pitch + col) * 2);
}

// Swizzled 64B-row tile addressing (GEMM core): rows x 32 bf16, no padding.
__device__ __forceinline__ uint32_t sw64(int row, int chunk) {
    return (uint32_t)((row << 6) + (((chunk ^ (row >> 1)) & 3) << 4));
}

__device__ __forceinline__ void st_pair_split(__nv_bfloat16* gh, __nv_bfloat16* gl,
                                              size_t off, float x0, float x1) {
    __nv_bfloat16 h0 = __float2bfloat16_rn(x0), h1 = __float2bfloat16_rn(x1);
    __nv_bfloat16 l0 = __float2bfloat16_rn(x0 - __bfloat162float(h0));
    __nv_bfloat16 l1 = __float2bfloat16_rn(x1 - __bfloat162float(h1));
    *(__nv_bfloat162*)(gh + off) = __halves2bfloat162(h0, h1);
    *(__nv_bfloat162*)(gl + off) = __halves2bfloat162(l0, l1);
}

// ---------------------------------------------------------------------------
// Merged setup: split all 9 fp32 arrays -> bf16 hi/lo in ONE launch.
// ---------------------------------------------------------------------------
__global__ void __launch_bounds__(256)
split_all(const float4* __restrict__ Wq, const float4* __restrict__ Wk,
          const float4* __restrict__ Wv, const float4* __restrict__ Wp,
          const float4* __restrict__ Wo,
          const float4* __restrict__ q, const float4* __restrict__ k,
          const float4* __restrict__ v, const float4* __restrict__ p)
{
    const int bid = blockIdx.x;
    const float4* src;
    uint2 *dh, *dl;
    int i, n4;
    if (bid < 5120) {
        const int w = bid >> 10;
        src = (w == 0) ? Wq : (w == 1) ? Wk : (w == 2) ? Wv : (w == 3) ? Wp : Wo;
        dh = (uint2*)(g_wh + w * 1048576);
        dl = (uint2*)(g_wl + w * 1048576);
        i = (bid & 1023) * 256 + threadIdx.x;
        n4 = 262144;
    } else if (bid < 9216) {
        src = q; dh = (uint2*)(g_inh + OIQ); dl = (uint2*)(g_inl + OIQ);
        i = (bid - 5120) * 256 + threadIdx.x; n4 = 1048576;
    } else if (bid < 13312) {
        src = k; dh = (uint2*)(g_inh + OIK); dl = (uint2*)(g_inl + OIK);
        i = (bid - 9216) * 256 + threadIdx.x; n4 = 1048576;
    } else if (bid < 17408) {
        src = v; dh = (uint2*)(g_inh + OIV); dl = (uint2*)(g_inl + OIV);
        i = (bid - 13312) * 256 + threadIdx.x; n4 = 1048576;
    } else {
        src = p; dh = (uint2*)(g_inh + OIP); dl = (uint2*)(g_inl + OIP);
        i = (bid - 17408) * 256 + threadIdx.x; n4 = 524032;
    }
    if (i >= n4) return;
    const float4 val = src[i];
    __nv_bfloat16 h0 = __float2bfloat16_rn(val.x), h1 = __float2bfloat16_rn(val.y);
    __nv_bfloat16 h2 = __float2bfloat16_rn(val.z), h3 = __float2bfloat16_rn(val.w);
    __nv_bfloat16 l0 = __float2bfloat16_rn(val.x - __bfloat162float(h0));
    __nv_bfloat16 l1 = __float2bfloat16_rn(val.y - __bfloat162float(h1));
    __nv_bfloat16 l2 = __float2bfloat16_rn(val.z - __bfloat162float(h2));
    __nv_bfloat16 l3 = __float2bfloat16_rn(val.w - __bfloat162float(h3));
    uint2 H, L;
    H.x = (us16(h1) << 16) | us16(h0); H.y = (us16(h3) << 16) | us16(h2);
    L.x = (us16(l1) << 16) | us16(l0); L.y = (us16(l3) << 16) | us16(l2);
    dh[i] = H; dl[i] = L;
}

// ---------------------------------------------------------------------------
// Pure-bf16 GEMM core (bf16x3): CTA 128x256, 8 warps, warp tile 64x64.
// Swizzled smem, 3-stage cp.async pipeline, ONE barrier per K-chunk,
// prefetch distance 2 chunks. 6 MMA per ldmatrix (was 4).
// Stage layout: Ah(8K) Al(8K) Bh(16K) Bl(16K) = 48K; 3 stages = 144K.
// ---------------------------------------------------------------------------
#define GOF_AL 8192
#define GOF_BH 16384
#define GOF_BL 32768
#define GSTAGE 49152
#define GSM_BYTES (3 * GSTAGE)

__device__ __forceinline__ void gemm_core_bf(
    const __nv_bfloat16* __restrict__ Ah, const __nv_bfloat16* __restrict__ Al,
    const __nv_bfloat16* __restrict__ Bh, const __nv_bfloat16* __restrict__ Bl,
    int m0, int n0, int M, char* smc, float acc[4][8][4])
{
    const uint32_t sb = smem_u32(smc);
    const int tid = threadIdx.x;
    const int lane = tid & 31;
    const int wid = tid >> 5;
    const int wm = wid >> 2, wn = wid & 3;   // warp tile: rows wm*64, cols wn*64

    // 12 cp.async granules per thread per chunk (3072 total = 48KB)
    const __nv_bfloat16* gsrc[12];
    uint32_t soff[12];
    #pragma unroll
    for (int j = 0; j < 12; j++) {
        const int f = tid + 256 * j;
        const int tile = (f < 512) ? 0 : (f < 1024) ? 1 : (f < 2048) ? 2 : 3;
        const int idx = (tile < 2) ? (f & 511) : ((f - 1024) & 1023);
        const int row = idx >> 2;
        const int ch = idx & 3;
        int r = ((tile < 2) ? m0 : n0) + row;
        if (tile < 2 && r > M - 1) r = M - 1;
        const __nv_bfloat16* base = (tile == 0) ? Ah : (tile == 1) ? Al : (tile == 2) ? Bh : Bl;
        gsrc[j] = base + (size_t)r * C_DIM + ch * 8;
        const uint32_t toff = (tile == 0) ? 0u : (tile == 1) ? (uint32_t)GOF_AL
                             : (tile == 2) ? (uint32_t)GOF_BH : (uint32_t)GOF_BL;
        soff[j] = toff + sw64(row, ch);
    }

    // Prologue: chunk 0 -> stage 0, chunk 1 -> stage 1
    #pragma unroll
    for (int j = 0; j < 12; j++) cp_async16(sb + soff[j], gsrc[j], true);
    cp_commit();
    #pragma unroll
    for (int j = 0; j < 12; j++) cp_async16(sb + GSTAGE + soff[j], gsrc[j] + 32, true);
    cp_commit();

    int stage = 0;
    for (int kc = 0; kc < 32; kc++) {
        if (kc < 31) cp_wait<1>(); else cp_wait<0>();
        __syncthreads();
        if (kc + 2 < 32) {
            const int pst = (stage + 2 >= 3) ? stage - 1 : stage + 2;
            const uint32_t pb = sb + (uint32_t)pst * GSTAGE;
            const int kof = (kc + 2) * 32;
            #pragma unroll
            for (int j = 0; j < 12; j++)
                cp_async16(pb + soff[j], gsrc[j] + kof, true);
            cp_commit();
        }
        const uint32_t sab = sb + (uint32_t)stage * GSTAGE;
        #pragma unroll
        for (int ks = 0; ks < 2; ks++) {
            const int c0 = ks * 2;
            // B fragments: 8 n8-tiles (64 cols), hi+lo = 8 ldsm
            uint32_t bh[4][4], bl[4][4];
            #pragma unroll
            for (int p = 0; p < 4; p++) {
                const int brow = wn * 64 + p * 16 + (lane & 7) + ((lane >> 4) << 3);
                const int bch = c0 + ((lane >> 3) & 1);
                const uint32_t ba = sab + GOF_BH + sw64(brow, bch);
                ldsm_x4(bh[p], ba);
                ldsm_x4(bl[p], ba + (GOF_BL - GOF_BH));
            }
            #pragma unroll
            for (int mt = 0; mt < 4; mt++) {
                const int arow = wm * 64 + mt * 16 + (lane & 15);
                const int ach = c0 + (lane >> 4);
                const uint32_t aa = sab + sw64(arow, ach);
                uint32_t ah[4], al[4];
                ldsm_x4(ah, aa);
                ldsm_x4(al, aa + GOF_AL);
                #pragma unroll
                for (int nt = 0; nt < 8; nt++) {
                    const uint32_t* bhp = &bh[nt >> 1][(nt & 1) * 2];
                    const uint32_t* blp = &bl[nt >> 1][(nt & 1) * 2];
                    mma_bf16(acc[mt][nt], ah, bhp);
                    mma_bf16(acc[mt][nt], ah, blp);
                    mma_bf16(acc[mt][nt], al, bhp);
                }
            }
        }
        stage = (stage + 1 >= 3) ? 0 : stage + 1;
    }
}

// ---------------------------------------------------------------------------
// Mega projection: q,k,v,p in one launch (448 CTAs, tile 128x256).
// ---------------------------------------------------------------------------
__global__ void __launch_bounds__(256, 1)
proj_mega(const float* __restrict__ bq, const float* __restrict__ bk,
          const float* __restrict__ bv, const float* __restrict__ pbu)
{
    extern __shared__ char smc[];
    const int id = blockIdx.x;
    int op, mi, ni;
    if (id < 384) { op = id >> 7; const int r = id & 127; mi = r >> 2; ni = r & 3; }
    else          { op = 3; const int r = id - 384; mi = r >> 2; ni = r & 3; }

    const int inoff = (op == 0) ? OIQ : (op == 1) ? OIK : (op == 2) ? OIV : OIP;
    const int woff  = op * 1048576;
    const int M = (op == 3) ? P_DIM : BT_DIM;
    const int m0 = mi * 128, n0 = ni * 256;

    float acc[4][8][4] = {};
    gemm_core_bf(g_inh + inoff, g_inl + inoff, g_wh + woff, g_wl + woff,
                 m0, n0, M, smc, acc);

    const int lane = threadIdx.x & 31, wid = threadIdx.x >> 5;
    const int g = lane >> 2, tg = lane & 3, wm = wid >> 2, wn = wid & 3;
    __nv_bfloat16* gh = (op == 0) ? g_quh : (op == 1) ? g_kh : (op == 2) ? g_vh : g_ph;
    __nv_bfloat16* gl = (op == 0) ? g_qul : (op == 1) ? g_kl : (op == 2) ? g_vl : g_pl;

    #pragma unroll
    for (int mt = 0; mt < 4; mt++) {
        const int r0 = m0 + wm * 64 + mt * 16 + g;
        const int r1 = r0 + 8;
        #pragma unroll
        for (int nt = 0; nt < 8; nt++) {
            const int col = n0 + wn * 64 + nt * 8 + 2 * tg;
            float b0 = 0.f, b1 = 0.f;
            if (op == 0)      { b0 = bq[col] + pbu[col]; b1 = bq[col + 1] + pbu[col + 1]; }
            else if (op == 1) { b0 = bk[col]; b1 = bk[col + 1]; }
            else if (op == 2) { b0 = bv[col]; b1 = bv[col + 1]; }
            float x0 = acc[mt][nt][0] + b0, x1 = acc[mt][nt][1] + b1;
            float x2 = acc[mt][nt][2] + b0, x3 = acc[mt][nt][3] + b1;
            if (op == 0) { x0 *= 0.125f; x1 *= 0.125f; x2 *= 0.125f; x3 *= 0.125f; }
            if (r0 < M) st_pair_split(gh, gl, (size_t)r0 * C_DIM + col, x0, x1);
            if (r1 < M) st_pair_split(gh, gl, (size_t)r1 * C_DIM + col, x2, x3);
        }
    }
}

// Output projection: A = attention out (bf16 hi/lo), writes fp32 d_out.
__global__ void __launch_bounds__(256, 1)
gemm_out(const float* __restrict__ bias, float* __restrict__ Cout)
{
    extern __shared__ char smc[];
    const int mi = blockIdx.x >> 2, ni = blockIdx.x & 3;
    const int m0 = mi * 128, n0 = ni * 256;
    float acc[4][8][4] = {};
    gemm_core_bf(g_xh, g_xl, g_wh + OWO, g_wl + OWO, m0, n0, BT_DIM, smc, acc);

    const int lane = threadIdx.x & 31, wid = threadIdx.x >> 5;
    const int g = lane >> 2, tg = lane & 3, wm = wid >> 2, wn = wid & 3;
    #pragma unroll
    for (int mt = 0; mt < 4; mt++) {
        const int r0 = m0 + wm * 64 + mt * 16 + g;
        #pragma unroll
        for (int nt = 0; nt < 8; nt++) {
            const int col = n0 + wn * 64 + nt * 8 + 2 * tg;
            const float b0 = bias[col], b1 = bias[col + 1];
            *(float2*)(Cout + (size_t)r0 * C_DIM + col) =
                make_float2(acc[mt][nt][0] + b0, acc[mt][nt][1] + b1);
            *(float2*)(Cout + (size_t)(r0 + 8) * C_DIM + col) =
                make_float2(acc[mt][nt][2] + b0, acc[mt][nt][3] + b1);
        }
    }
}

// ---------------------------------------------------------------------------
// Attention: unchanged from Round 9 (validated).
// ---------------------------------------------------------------------------
#define ATP 72
#define OQUH 0
#define OQUL 9216
#define OKH  18432
#define OKL  27648
#define OVH  36864
#define OVL  46080
#define OBH  55296
#define OBL  73728
#define OPH  92160
#define OPL  101376
#define OEV  110592
#define ODL  111104
#define ATT_BYTES 111360

__global__ void __launch_bounds__(128)
attn_bf16(const float* __restrict__ pbu, const float* __restrict__ pbv)
{
    extern __shared__ char smc[];
    const uint32_t sb = smem_u32(smc);
    const int tid = threadIdx.x;
    const int wid = tid >> 5;
    const int lane = tid & 31;
    const int g = lane >> 2, tg = lane & 3;
    const int t0 = blockIdx.x * 64;
    const int b = (int)blockIdx.y >> 4;
    const int h = (int)blockIdx.y & 15;
    const int row0w = wid * 16;
    const int row0g = row0w + g;
    const int cbase = 48 - row0w;

    {
        const int w0 = 960 - t0;
        #pragma unroll
        for (int jj = 0; jj < 8; jj++) {
            const int f = tid + 128 * jj;
            const int half = f >> 9, rem = f & 511, row = rem >> 3, ch = rem & 7;
            const __nv_bfloat16* src = half ? g_kl : g_kh;
            const uint32_t dst = sb + (half ? OKL : OKH);
            cp_async16(dst + (uint32_t)((row * ATP + ch * 8) * 2),
                       src + ((size_t)row * B_DIM + b) * C_DIM + h * 64 + ch * 8, true);
        }
        #pragma unroll
        for (int jj = 0; jj < 16; jj++) {
            const int f = tid + 128 * jj;
            const int half = f >> 10, rem = f & 1023, row = rem >> 3, ch = rem & 7;
            if (row < 127) {
                const int pr = w0 + row;
                const int slot = pr & 127;
                const __nv_bfloat16* src = half ? g_pl : g_ph;
                const uint32_t dst = sb + (half ? OBL : OBH);
                cp_async16(dst + (uint32_t)((slot * ATP + ch * 8) * 2),
                           src + (size_t)pr * C_DIM + h * 64 + ch * 8, true);
            }
        }
        cp_commit();
        #pragma unroll
        for (int jj = 0; jj < 8; jj++) {
            const int f = tid + 128 * jj;
            const int half = f >> 9, rem = f & 511, row = rem >> 3, ch = rem & 7;
            const __nv_bfloat16* src = half ? g_qul : g_quh;
            const uint32_t dst = sb + (half ? OQUL : OQUH);
            cp_async16(dst + (uint32_t)((row * ATP + ch * 8) * 2),
                       src + ((size_t)(t0 + row) * B_DIM + b) * C_DIM + h * 64 + ch * 8, true);
        }
        cp_commit();
        #pragma unroll
        for (int jj = 0; jj < 8; jj++) {
            const int f = tid + 128 * jj;
            const int half = f >> 9, rem = f & 511, row = rem >> 3, ch = rem & 7;
            const __nv_bfloat16* src = half ? g_vl : g_vh;
            const uint32_t dst = sb + (half ? OVL : OVH);
            cp_async16(dst + (uint32_t)((row * ATP + ch * 8) * 2),
                       src + ((size_t)row * B_DIM + b) * C_DIM + h * 64 + ch * 8, true);
        }
        cp_commit();
    }

    if (tid < 64)
        ((float*)(smc + ODL))[tid] = (pbv[h * 64 + tid] - pbu[h * 64 + tid]) * 0.125f;

    cp_wait<1>();
    __syncthreads();

    uint32_t quh[4][4], qul[4][4];
    #pragma unroll
    for (int k = 0; k < 4; k++) {
        const uint32_t aa = a_addr(sb + OQUH, row0w, k * 16, lane, ATP);
        ldsm_x4(quh[k], aa);
        ldsm_x4(qul[k], aa + (OQUL - OQUH));
    }

    float oacc[8][4];
    #pragma unroll
    for (int nt = 0; nt < 8; nt++)
        #pragma unroll
        for (int r = 0; r < 4; r++) oacc[nt][r] = 0.f;
    float lp0 = 0.f, lp1 = 0.f;

    for (int it = 0; it < 16; it++) {
        const int s0 = it * 64;
        const int off = (s0 - t0 + 960) & 127;
        const int s0n = (s0 + 64 < T_DIM) ? s0 + 64 : s0;
        const int wnx = s0n - t0 + 960;

        cp_wait<1>();
        __syncthreads();

        if (tid < 127) {
            const int phys = (off + tid) & 127;
            const __nv_bfloat162* bh2 = (const __nv_bfloat162*)((__nv_bfloat16*)(smc + OBH) + phys * ATP);
            const __nv_bfloat162* bl2 = (const __nv_bfloat162*)((__nv_bfloat16*)(smc + OBL) + phys * ATP);
            const float2* dl2 = (const float2*)(smc + ODL);
            float s = 0.f;
            #pragma unroll
            for (int d2 = 0; d2 < 32; d2++) {
                const __nv_bfloat162 hh = bh2[d2], ll = bl2[d2];
                const float2 dv = dl2[d2];
                s = fmaf(__bfloat162float(hh.x) + __bfloat162float(ll.x), dv.x, s);
                s = fmaf(__bfloat162float(hh.y) + __bfloat162float(ll.y), dv.y, s);
            }
            ((float*)(smc + OEV))[tid] = s;
        }

        float sacc[8][4];
        #pragma unroll
        for (int nt = 0; nt < 8; nt++)
            #pragma unroll
            for (int r = 0; r < 4; r++) sacc[nt][r] = 0.f;
        #pragma unroll
        for (int k = 0; k < 4; k++) {
            #pragma unroll
            for (int p = 0; p < 4; p++) {
                const uint32_t ba = b_addr(sb + OKH, p * 16, k * 16, lane, ATP);
                uint32_t bh4[4], bl4[4];
                ldsm_x4(bh4, ba);
                ldsm_x4(bl4, ba + (OKL - OKH));
                mma_bf16(sacc[2 * p],     quh[k], bh4);     mma_bf16(sacc[2 * p],     quh[k], bl4);
                mma_bf16(sacc[2 * p],     qul[k], bh4);
                mma_bf16(sacc[2 * p + 1], quh[k], bh4 + 2); mma_bf16(sacc[2 * p + 1], quh[k], bl4 + 2);
                mma_bf16(sacc[2 * p + 1], qul[k], bh4 + 2);
            }
        }
        __syncthreads();

        #pragma unroll
        for (int jj = 0; jj < 8; jj++) {
            const int f = tid + 128 * jj;
            const int half = f >> 9, rem = f & 511, row = rem >> 3, ch = rem & 7;
            const __nv_bfloat16* src = half ? g_kl : g_kh;
            const uint32_t dst = sb + (half ? OKL : OKH);
            cp_async16(dst + (uint32_t)((row * ATP + ch * 8) * 2),
                       src + ((size_t)(s0n + row) * B_DIM + b) * C_DIM + h * 64 + ch * 8, true);
        }
        cp_commit();

        float gacc[10][4];
        #pragma unroll
        for (int nt = 0; nt < 10; nt++)
            #pragma unroll
            for (int r = 0; r < 4; r++) gacc[nt][r] = 0.f;
        #pragma unroll
        for (int k = 0; k < 4; k++) {
            #pragma unroll
            for (int p = 0; p < 5; p++) {
                const int basep = (off + cbase + p * 16) & 127;
                const uint32_t ba = b_addr(sb + OBH, basep, k * 16, lane, ATP);
                uint32_t bh4[4], bl4[4];
                ldsm_x4(bh4, ba);
                ldsm_x4(bl4, ba + (OBL - OBH));
                mma_bf16(gacc[2 * p],     quh[k], bh4);     mma_bf16(gacc[2 * p],     quh[k], bl4);
                mma_bf16(gacc[2 * p],     qul[k], bh4);
                mma_bf16(gacc[2 * p + 1], quh[k], bh4 + 2); mma_bf16(gacc[2 * p + 1], quh[k], bl4 + 2);
                mma_bf16(gacc[2 * p + 1], qul[k], bh4 + 2);
            }
        }
        {
            float* BD = (float*)(smc + OPH);
            const float* EV = (const float*)(smc + OEV);
            #pragma unroll
            for (int nt = 0; nt < 10; nt++)
                #pragma unroll
                for (int r2 = 0; r2 < 2; r2++) {
                    const int t = row0g + 8 * r2;
                    #pragma unroll
                    for (int cc = 0; cc < 2; cc++) {
                        const int c = cbase + nt * 8 + 2 * tg + cc;
                        const int s = c - 63 + t;
                        if (s >= 0 && s < 64)
                            BD[t * 68 + s] = gacc[nt][r2 * 2 + cc] + EV[c];
                    }
                }
        }
        __syncthreads();

        #pragma unroll
        for (int jj = 0; jj < 8; jj++) {
            const int f = tid + 128 * jj;
            const int half = f >> 9, rem = f & 511, row = rem >> 3, ch = rem & 7;
            const int pr = wnx + 63 + row;
            const int slot = pr & 127;
            const __nv_bfloat16* src = half ? g_pl : g_ph;
            const uint32_t dst = sb + (half ? OBL : OBH);
            cp_async16(dst + (uint32_t)((slot * ATP + ch * 8) * 2),
                       src + (size_t)pr * C_DIM + h * 64 + ch * 8, true);
        }
        cp_commit();

        const float* BD = (const float*)(smc + OPH);
        float pval[8][4];
        #pragma unroll
        for (int nt = 0; nt < 8; nt++)
            #pragma unroll
            for (int r2 = 0; r2 < 2; r2++) {
                const int t = row0g + 8 * r2;
                #pragma unroll
                for (int cc = 0; cc < 2; cc++) {
                    const int s = nt * 8 + 2 * tg + cc;
                    float v = sacc[nt][r2 * 2 + cc] + BD[t * 68 + s];
                    v = __expf(fminf(v, 60.f));
                    pval[nt][r2 * 2 + cc] = v;
                    if (r2 == 0) lp0 += v; else lp1 += v;
                }
            }
        __syncthreads();   // MANDATORY: BD aliases P tiles across warps
        {
            __nv_bfloat16* Ph = (__nv_bfloat16*)(smc + OPH);
            __nv_bfloat16* Pl = (__nv_bfloat16*)(smc + OPL);
            #pragma unroll
            for (int nt = 0; nt < 8; nt++)
                #pragma unroll
                for (int r2 = 0; r2 < 2; r2++) {
                    const int t = row0g + 8 * r2;
                    const int s = nt * 8 + 2 * tg;
                    st_pair_split(Ph, Pl, (size_t)(t * ATP + s),
                                  pval[nt][r2 * 2], pval[nt][r2 * 2 + 1]);
                }
        }
        cp_wait<2>();
        __syncthreads();

        #pragma unroll
        for (int k = 0; k < 4; k++) {
            const uint32_t pa = a_addr(sb + OPH, row0w, k * 16, lane, ATP);
            uint32_t aph[4], apl[4];
            ldsm_x4(aph, pa);
            ldsm_x4(apl, pa + (OPL - OPH));
            #pragma unroll
            for (int p = 0; p < 4; p++) {
                const uint32_t va = a_addr(sb + OVH, k * 16, p * 16, lane, ATP);
                uint32_t vh4[4], vl4[4];
                ldsm_x4t(vh4, va);
                ldsm_x4t(vl4, va + (OVL - OVH));
                mma_bf16(oacc[2 * p],     aph, vh4);     mma_bf16(oacc[2 * p],     aph, vl4);
                mma_bf16(oacc[2 * p],     apl, vh4);
                mma_bf16(oacc[2 * p + 1], aph, vh4 + 2); mma_bf16(oacc[2 * p + 1], aph, vl4 + 2);
                mma_bf16(oacc[2 * p + 1], apl, vh4 + 2);
            }
        }
        __syncthreads();

        #pragma unroll
        for (int jj = 0; jj < 8; jj++) {
            const int f = tid + 128 * jj;
            const int half = f >> 9, rem = f & 511, row = rem >> 3, ch = rem & 7;
            const __nv_bfloat16* src = half ? g_vl : g_vh;
            const uint32_t dst = sb + (half ? OVL : OVH);
            cp_async16(dst + (uint32_t)((row * ATP + ch * 8) * 2),
                       src + ((size_t)(s0n + row) * B_DIM + b) * C_DIM + h * 64 + ch * 8, true);
        }
        cp_commit();
    }
    cp_wait<0>();

    lp0 += __shfl_xor_sync(0xffffffffu, lp0, 1);
    lp0 += __shfl_xor_sync(0xffffffffu, lp0, 2);
    lp1 += __shfl_xor_sync(0xffffffffu, lp1, 1);
    lp1 += __shfl_xor_sync(0xffffffffu, lp1, 2);
    const float inv0 = 1.f / lp0;
    const float inv1 = 1.f / lp1;

    #pragma unroll
    for (int nt = 0; nt < 8; nt++) {
        const int col = h * 64 + nt * 8 + 2 * tg;
        const size_t o0 = ((size_t)(t0 + row0g) * B_DIM + b) * C_DIM + col;
        const size_t o1 = ((size_t)(t0 + row0g + 8) * B_DIM + b) * C_DIM + col;
        st_pair_split(g_xh, g_xl, o0, oacc[nt][0] * inv0, oacc[nt][1] * inv0);
        st_pair_split(g_xh, g_xl, o1, oacc[nt][2] * inv1, oacc[nt][3] * inv1);
    }
}

// ---------------------------------------------------------------------------
// Launch
// ---------------------------------------------------------------------------
extern "C" void kernel_launch(void* const* d_in, const int* in_sizes, int n_in,
                              void* d_out, int out_size)
{
    const float* query   = (const float*)d_in[0];
    const float* key     = (const float*)d_in[1];
    const float* value   = (const float*)d_in[2];
    const float* pos_emb = (const float*)d_in[3];
    const float* Wq      = (const float*)d_in[4];
    const float* bq      = (const float*)d_in[5];
    const float* Wk      = (const float*)d_in[6];
    const float* bk      = (const float*)d_in[7];
    const float* Wv      = (const float*)d_in[8];
    const float* bv      = (const float*)d_in[9];
    const float* Wp      = (const float*)d_in[10];
    const float* Wo      = (const float*)d_in[11];
    const float* bo      = (const float*)d_in[12];
    const float* pbu     = (const float*)d_in[13];
    const float* pbv     = (const float*)d_in[14];
    float* out = (float*)d_out;

    cudaFuncSetAttribute(proj_mega, cudaFuncAttributeMaxDynamicSharedMemorySize, GSM_BYTES);
    cudaFuncSetAttribute(gemm_out,  cudaFuncAttributeMaxDynamicSharedMemorySize, GSM_BYTES);
    cudaFuncSetAttribute(attn_bf16, cudaFuncAttributeMaxDynamicSharedMemorySize, ATT_BYTES);

    split_all<<<19455, 256>>>((const float4*)Wq, (const float4*)Wk, (const float4*)Wv,
                              (const float4*)Wp, (const float4*)Wo,
                              (const float4*)query, (const float4*)key,
                              (const float4*)value, (const float4*)pos_emb);

    proj_mega<<<448, 256, GSM_BYTES>>>(bq, bk, bv, pbu);
    attn_bf16<<<dim3(16, 64), 128, ATT_BYTES>>>(pbu, pbv);
    gemm_out<<<128, 256, GSM_BYTES>>>(bo, out);
}